// round 1
// baseline (speedup 1.0000x reference)
#include <cuda_runtime.h>
#include <cuda_bf16.h>

// GCNConv: out = D_in^{-1/2} * A * (D_out^{-1/2} * (X @ W)) + bias
// N=100000, C_in=C_out=128, DEG=16 (but computed from ptrs at runtime).
//
// Stage 1 (gemm_norm_kernel): h = (X @ W) * out_norm   -> scratch g_h
// Stage 2 (aggregate_kernel): out[i] = in_norm[i] * sum_e h[colind[e]] + bias

#define C128 128
#define MAX_N 100000

// scratch: h = (x @ w) * out_norm, fp32 [N, 128]
__device__ float g_h[(size_t)MAX_N * C128];

// ---------------------------------------------------------------------------
// GEMM: block computes 64 rows x 128 cols. 256 threads, each 4 rows x 8 cols.
// W (128x128 fp32, 64KB) fully staged in smem; A tile staged transposed.
// ---------------------------------------------------------------------------
__global__ __launch_bounds__(256) void gemm_norm_kernel(
    const float* __restrict__ x,      // [n, 128]
    const float* __restrict__ w,      // [128, 128] row-major (k, c)
    const int*   __restrict__ colptr, // [n+1]  (out-degree)
    float*       __restrict__ h,      // [n, 128]
    int n)
{
    extern __shared__ float smem[];
    float* Ws = smem;                 // [128][128]   (k-major)  64KB
    float* As = smem + 128 * 128;     // [128][65]    As[k*65+row] 33.3KB

    const int tid = threadIdx.x;
    const int block_row = blockIdx.x * 64;

    // --- stage W: 16384 floats = 4096 float4, 256 threads -> 16 iters ---
    {
        const float4* w4 = reinterpret_cast<const float4*>(w);
        float4* Ws4 = reinterpret_cast<float4*>(Ws);
        #pragma unroll
        for (int i = 0; i < 16; i++)
            Ws4[i * 256 + tid] = w4[i * 256 + tid];
    }

    // --- stage A tile transposed: 64 rows x 128 k = 2048 float4 ---
    {
        const float4* x4 = reinterpret_cast<const float4*>(x);
        #pragma unroll
        for (int it = 0; it < 8; it++) {
            int elem = it * 256 + tid;       // float4 unit index in tile
            int row  = elem >> 5;            // 0..63
            int k4   = elem & 31;            // float4 column
            int grow = block_row + row;
            float4 v;
            if (grow < n) v = x4[(size_t)grow * 32 + k4];
            else          v = make_float4(0.f, 0.f, 0.f, 0.f);
            int kb = k4 * 4;
            As[(kb + 0) * 65 + row] = v.x;
            As[(kb + 1) * 65 + row] = v.y;
            As[(kb + 2) * 65 + row] = v.z;
            As[(kb + 3) * 65 + row] = v.w;
        }
    }
    __syncthreads();

    // --- compute: thread -> 4 rows x 8 cols ---
    const int row_t = tid >> 4;       // 0..15
    const int col_t = tid & 15;       // 0..15
    const int r0 = row_t * 4;
    const int c0 = col_t * 8;

    float acc[4][8];
    #pragma unroll
    for (int i = 0; i < 4; i++)
        #pragma unroll
        for (int j = 0; j < 8; j++)
            acc[i][j] = 0.f;

    #pragma unroll 8
    for (int k = 0; k < 128; k++) {
        float a0 = As[k * 65 + r0 + 0];
        float a1 = As[k * 65 + r0 + 1];
        float a2 = As[k * 65 + r0 + 2];
        float a3 = As[k * 65 + r0 + 3];
        float4 b0 = *reinterpret_cast<const float4*>(&Ws[k * 128 + c0]);
        float4 b1 = *reinterpret_cast<const float4*>(&Ws[k * 128 + c0 + 4]);
        float bv[8] = {b0.x, b0.y, b0.z, b0.w, b1.x, b1.y, b1.z, b1.w};
        float av[4] = {a0, a1, a2, a3};
        #pragma unroll
        for (int i = 0; i < 4; i++)
            #pragma unroll
            for (int j = 0; j < 8; j++)
                acc[i][j] = fmaf(av[i], bv[j], acc[i][j]);
    }

    // --- epilogue: scale by out_norm (1/sqrt(out-degree)) and store ---
    #pragma unroll
    for (int i = 0; i < 4; i++) {
        int grow = block_row + r0 + i;
        if (grow < n) {
            float deg = (float)(colptr[grow + 1] - colptr[grow]);
            float s = (deg > 0.f) ? rsqrtf(deg) : 0.f;
            float4 o0 = make_float4(acc[i][0] * s, acc[i][1] * s,
                                    acc[i][2] * s, acc[i][3] * s);
            float4 o1 = make_float4(acc[i][4] * s, acc[i][5] * s,
                                    acc[i][6] * s, acc[i][7] * s);
            float4* hp = reinterpret_cast<float4*>(&h[(size_t)grow * 128 + c0]);
            hp[0] = o0;
            hp[1] = o1;
        }
    }
}

// ---------------------------------------------------------------------------
// Aggregation: 4 nodes per block, 32 lanes per node, float4 per lane.
// out[i] = in_norm[i] * sum_{e in [rowptr[i], rowptr[i+1])} h[colind[e]] + bias
// ---------------------------------------------------------------------------
__global__ __launch_bounds__(128) void aggregate_kernel(
    const float* __restrict__ h,      // [n, 128]
    const int*   __restrict__ rowptr, // [n+1]
    const int*   __restrict__ colind, // [E]
    const float* __restrict__ bias,   // [128]
    float*       __restrict__ out,    // [n, 128]
    int n)
{
    const int node = blockIdx.x * 4 + (threadIdx.x >> 5);
    const int lane = threadIdx.x & 31;
    if (node >= n) return;

    const int beg = rowptr[node];
    const int end = rowptr[node + 1];

    const float4* h4 = reinterpret_cast<const float4*>(h);

    float4 a0 = make_float4(0.f, 0.f, 0.f, 0.f);
    float4 a1 = make_float4(0.f, 0.f, 0.f, 0.f);
    float4 a2 = make_float4(0.f, 0.f, 0.f, 0.f);
    float4 a3 = make_float4(0.f, 0.f, 0.f, 0.f);

    int e = beg;
    for (; e + 4 <= end; e += 4) {
        int i0 = __ldg(&colind[e + 0]);
        int i1 = __ldg(&colind[e + 1]);
        int i2 = __ldg(&colind[e + 2]);
        int i3 = __ldg(&colind[e + 3]);
        float4 v0 = h4[(size_t)i0 * 32 + lane];
        float4 v1 = h4[(size_t)i1 * 32 + lane];
        float4 v2 = h4[(size_t)i2 * 32 + lane];
        float4 v3 = h4[(size_t)i3 * 32 + lane];
        a0.x += v0.x; a0.y += v0.y; a0.z += v0.z; a0.w += v0.w;
        a1.x += v1.x; a1.y += v1.y; a1.z += v1.z; a1.w += v1.w;
        a2.x += v2.x; a2.y += v2.y; a2.z += v2.z; a2.w += v2.w;
        a3.x += v3.x; a3.y += v3.y; a3.z += v3.z; a3.w += v3.w;
    }
    for (; e < end; e++) {
        int i0 = __ldg(&colind[e]);
        float4 v0 = h4[(size_t)i0 * 32 + lane];
        a0.x += v0.x; a0.y += v0.y; a0.z += v0.z; a0.w += v0.w;
    }

    float4 acc;
    acc.x = (a0.x + a1.x) + (a2.x + a3.x);
    acc.y = (a0.y + a1.y) + (a2.y + a3.y);
    acc.z = (a0.z + a1.z) + (a2.z + a3.z);
    acc.w = (a0.w + a1.w) + (a2.w + a3.w);

    float deg = (float)(end - beg);
    float s = (deg > 0.f) ? rsqrtf(deg) : 0.f;

    float4 b = reinterpret_cast<const float4*>(bias)[lane];
    float4 o;
    o.x = acc.x * s + b.x;
    o.y = acc.y * s + b.y;
    o.z = acc.z * s + b.z;
    o.w = acc.w * s + b.w;

    reinterpret_cast<float4*>(out)[(size_t)node * 32 + lane] = o;
}

// ---------------------------------------------------------------------------
// launch
// ---------------------------------------------------------------------------
extern "C" void kernel_launch(void* const* d_in, const int* in_sizes, int n_in,
                              void* d_out, int out_size)
{
    const float* x      = (const float*)d_in[0];
    const float* weight = (const float*)d_in[1];
    const float* bias   = (const float*)d_in[2];
    const int*   rowptr = (const int*)  d_in[3];
    const int*   colind = (const int*)  d_in[4];
    const int*   colptr = (const int*)  d_in[5];
    // d_in[6] = rowind (unused)

    const int n = in_sizes[3] - 1;   // rowptr has n+1 entries

    float* out = (float*)d_out;

    float* h_scratch = nullptr;
    cudaGetSymbolAddress((void**)&h_scratch, g_h);

    // GEMM: dynamic smem = W(128x128) + As(128x65)
    const int smem_bytes = (128 * 128 + 128 * 65) * (int)sizeof(float);
    cudaFuncSetAttribute(gemm_norm_kernel,
                         cudaFuncAttributeMaxDynamicSharedMemorySize, smem_bytes);

    int gemm_blocks = (n + 63) / 64;
    gemm_norm_kernel<<<gemm_blocks, 256, smem_bytes>>>(x, weight, colptr,
                                                       h_scratch, n);

    int agg_blocks = (n + 3) / 4;
    aggregate_kernel<<<agg_blocks, 128>>>(h_scratch, rowptr, colind, bias,
                                          out, n);
}

// round 2
// speedup vs baseline: 1.3113x; 1.3113x over previous
#include <cuda_runtime.h>
#include <cuda_bf16.h>

// GCNConv: out = D_in^{-1/2} * A * (D_out^{-1/2} * (X @ W)) + bias
// Stage 1: tf32x3 tensor-core GEMM  h = (X @ W) * out_norm   -> scratch g_h
// Stage 2: gather-aggregate         out[i] = in_norm * sum h[colind[e]] + bias

#define MAX_N 100000

__device__ float g_h[(size_t)MAX_N * 128];

// ---------------------------------------------------------------------------
// helpers
// ---------------------------------------------------------------------------
__device__ __forceinline__ unsigned f2tf32(float f) {
    unsigned r;
    asm("cvt.rna.tf32.f32 %0, %1;" : "=r"(r) : "f"(f));
    return r;
}

__device__ __forceinline__ void mma_tf32(float* c, const unsigned* a,
                                         unsigned b0, unsigned b1) {
    asm volatile(
        "mma.sync.aligned.m16n8k8.row.col.f32.tf32.tf32.f32 "
        "{%0,%1,%2,%3}, {%4,%5,%6,%7}, {%8,%9}, {%0,%1,%2,%3};"
        : "+f"(c[0]), "+f"(c[1]), "+f"(c[2]), "+f"(c[3])
        : "r"(a[0]), "r"(a[1]), "r"(a[2]), "r"(a[3]), "r"(b0), "r"(b1));
}

// ---------------------------------------------------------------------------
// GEMM: block = 64 rows x 128 cols, K=128 one-shot in smem.
// 256 threads = 8 warps: warp_m in [0,4) x warp_n in [0,2).
// Each warp: m16 x n64 = 8 (m16n8) tiles. tf32x3 compensation.
// A smem stride 132 (conflict-free a-frag), W smem stride 136 (conflict-free b-frag).
// ---------------------------------------------------------------------------
#define AS_STRIDE 132
#define WS_STRIDE 136

__global__ __launch_bounds__(256) void gemm_norm_kernel(
    const float* __restrict__ x,      // [n, 128]
    const float* __restrict__ w,      // [128, 128] row-major (k, c)
    const int*   __restrict__ colptr, // [n+1]  (out-degree)
    float*       __restrict__ h,      // [n, 128]
    int n)
{
    extern __shared__ float smem[];
    float* As = smem;                          // [64][132]
    float* Ws = smem + 64 * AS_STRIDE;         // [128][136]

    const int tid = threadIdx.x;
    const int block_row = blockIdx.x * 64;

    // --- stage A tile: 64 x 128 = 2048 float4 ---
    {
        const float4* x4 = reinterpret_cast<const float4*>(x);
        #pragma unroll
        for (int it = 0; it < 8; it++) {
            int elem = it * 256 + tid;
            int row  = elem >> 5;            // 0..63
            int col4 = elem & 31;
            int grow = block_row + row;
            float4 v = make_float4(0.f, 0.f, 0.f, 0.f);
            if (grow < n) v = x4[(size_t)grow * 32 + col4];
            *reinterpret_cast<float4*>(&As[row * AS_STRIDE + col4 * 4]) = v;
        }
    }
    // --- stage W: 128 x 128 = 4096 float4 ---
    {
        const float4* w4 = reinterpret_cast<const float4*>(w);
        #pragma unroll
        for (int it = 0; it < 16; it++) {
            int elem = it * 256 + tid;
            int row  = elem >> 5;            // 0..127
            int col4 = elem & 31;
            *reinterpret_cast<float4*>(&Ws[row * WS_STRIDE + col4 * 4]) =
                w4[elem];
        }
    }
    __syncthreads();

    const int warp_id = tid >> 5;
    const int lane    = tid & 31;
    const int warp_m  = warp_id & 3;          // 0..3 -> rows warp_m*16
    const int warp_n  = warp_id >> 2;         // 0..1 -> cols warp_n*64
    const int lg      = lane >> 2;            // lane group 0..7
    const int lt      = lane & 3;             // 0..3

    float acc[8][4];
    #pragma unroll
    for (int t = 0; t < 8; t++)
        #pragma unroll
        for (int j = 0; j < 4; j++)
            acc[t][j] = 0.f;

    const int arow = warp_m * 16 + lg;        // a-frag base row in tile
    const int nbase = warp_n * 64;

    #pragma unroll
    for (int ks = 0; ks < 16; ks++) {
        const int k0 = ks * 8;

        // A fragment (m16 x k8): 4 values, then hi/lo tf32 split
        float af[4];
        af[0] = As[(arow    ) * AS_STRIDE + k0 + lt    ];
        af[1] = As[(arow + 8) * AS_STRIDE + k0 + lt    ];
        af[2] = As[(arow    ) * AS_STRIDE + k0 + lt + 4];
        af[3] = As[(arow + 8) * AS_STRIDE + k0 + lt + 4];

        unsigned a_hi[4], a_lo[4];
        #pragma unroll
        for (int j = 0; j < 4; j++) {
            a_hi[j] = f2tf32(af[j]);
            a_lo[j] = f2tf32(af[j] - __uint_as_float(a_hi[j]));
        }

        #pragma unroll
        for (int t = 0; t < 8; t++) {
            const int n0 = nbase + t * 8;
            float bf0 = Ws[(k0 + lt    ) * WS_STRIDE + n0 + lg];
            float bf1 = Ws[(k0 + lt + 4) * WS_STRIDE + n0 + lg];
            unsigned bh0 = f2tf32(bf0);
            unsigned bh1 = f2tf32(bf1);
            unsigned bl0 = f2tf32(bf0 - __uint_as_float(bh0));
            unsigned bl1 = f2tf32(bf1 - __uint_as_float(bh1));

            mma_tf32(acc[t], a_hi, bh0, bh1);   // hi*hi
            mma_tf32(acc[t], a_hi, bl0, bl1);   // hi*lo
            mma_tf32(acc[t], a_lo, bh0, bh1);   // lo*hi
        }
    }

    // --- epilogue: scale rows by out_norm, store float2 per c-pair ---
    const int row0 = block_row + warp_m * 16 + lg;
    const int row1 = row0 + 8;
    float s0 = 0.f, s1 = 0.f;
    if (row0 < n) {
        float d = (float)(colptr[row0 + 1] - colptr[row0]);
        s0 = (d > 0.f) ? rsqrtf(d) : 0.f;
    }
    if (row1 < n) {
        float d = (float)(colptr[row1 + 1] - colptr[row1]);
        s1 = (d > 0.f) ? rsqrtf(d) : 0.f;
    }

    #pragma unroll
    for (int t = 0; t < 8; t++) {
        const int col = nbase + t * 8 + 2 * lt;
        if (row0 < n) {
            float2 v = make_float2(acc[t][0] * s0, acc[t][1] * s0);
            *reinterpret_cast<float2*>(&h[(size_t)row0 * 128 + col]) = v;
        }
        if (row1 < n) {
            float2 v = make_float2(acc[t][2] * s1, acc[t][3] * s1);
            *reinterpret_cast<float2*>(&h[(size_t)row1 * 128 + col]) = v;
        }
    }
}

// ---------------------------------------------------------------------------
// Aggregation: 8 nodes per block (256 threads), 32 lanes per node, float4/lane.
// ---------------------------------------------------------------------------
__global__ __launch_bounds__(256) void aggregate_kernel(
    const float* __restrict__ h,      // [n, 128]
    const int*   __restrict__ rowptr, // [n+1]
    const int*   __restrict__ colind, // [E]
    const float* __restrict__ bias,   // [128]
    float*       __restrict__ out,    // [n, 128]
    int n)
{
    const int node = blockIdx.x * 8 + (threadIdx.x >> 5);
    const int lane = threadIdx.x & 31;
    if (node >= n) return;

    const int beg = rowptr[node];
    const int end = rowptr[node + 1];

    const float4* h4 = reinterpret_cast<const float4*>(h);

    float4 a0 = make_float4(0.f, 0.f, 0.f, 0.f);
    float4 a1 = make_float4(0.f, 0.f, 0.f, 0.f);
    float4 a2 = make_float4(0.f, 0.f, 0.f, 0.f);
    float4 a3 = make_float4(0.f, 0.f, 0.f, 0.f);

    int e = beg;
    for (; e + 4 <= end; e += 4) {
        int i0 = __ldg(&colind[e + 0]);
        int i1 = __ldg(&colind[e + 1]);
        int i2 = __ldg(&colind[e + 2]);
        int i3 = __ldg(&colind[e + 3]);
        float4 v0 = h4[(size_t)i0 * 32 + lane];
        float4 v1 = h4[(size_t)i1 * 32 + lane];
        float4 v2 = h4[(size_t)i2 * 32 + lane];
        float4 v3 = h4[(size_t)i3 * 32 + lane];
        a0.x += v0.x; a0.y += v0.y; a0.z += v0.z; a0.w += v0.w;
        a1.x += v1.x; a1.y += v1.y; a1.z += v1.z; a1.w += v1.w;
        a2.x += v2.x; a2.y += v2.y; a2.z += v2.z; a2.w += v2.w;
        a3.x += v3.x; a3.y += v3.y; a3.z += v3.z; a3.w += v3.w;
    }
    for (; e < end; e++) {
        int i0 = __ldg(&colind[e]);
        float4 v0 = h4[(size_t)i0 * 32 + lane];
        a0.x += v0.x; a0.y += v0.y; a0.z += v0.z; a0.w += v0.w;
    }

    float4 acc;
    acc.x = (a0.x + a1.x) + (a2.x + a3.x);
    acc.y = (a0.y + a1.y) + (a2.y + a3.y);
    acc.z = (a0.z + a1.z) + (a2.z + a3.z);
    acc.w = (a0.w + a1.w) + (a2.w + a3.w);

    float deg = (float)(end - beg);
    float s = (deg > 0.f) ? rsqrtf(deg) : 0.f;

    float4 b = reinterpret_cast<const float4*>(bias)[lane];
    float4 o;
    o.x = acc.x * s + b.x;
    o.y = acc.y * s + b.y;
    o.z = acc.z * s + b.z;
    o.w = acc.w * s + b.w;

    reinterpret_cast<float4*>(out)[(size_t)node * 32 + lane] = o;
}

// ---------------------------------------------------------------------------
// launch
// ---------------------------------------------------------------------------
extern "C" void kernel_launch(void* const* d_in, const int* in_sizes, int n_in,
                              void* d_out, int out_size)
{
    const float* x      = (const float*)d_in[0];
    const float* weight = (const float*)d_in[1];
    const float* bias   = (const float*)d_in[2];
    const int*   rowptr = (const int*)  d_in[3];
    const int*   colind = (const int*)  d_in[4];
    const int*   colptr = (const int*)  d_in[5];

    const int n = in_sizes[3] - 1;

    float* out = (float*)d_out;

    float* h_scratch = nullptr;
    cudaGetSymbolAddress((void**)&h_scratch, g_h);

    const int smem_bytes = (64 * AS_STRIDE + 128 * WS_STRIDE) * (int)sizeof(float);
    cudaFuncSetAttribute(gemm_norm_kernel,
                         cudaFuncAttributeMaxDynamicSharedMemorySize, smem_bytes);

    int gemm_blocks = (n + 63) / 64;
    gemm_norm_kernel<<<gemm_blocks, 256, smem_bytes>>>(x, weight, colptr,
                                                       h_scratch, n);

    int agg_blocks = (n + 7) / 8;
    aggregate_kernel<<<agg_blocks, 256>>>(h_scratch, rowptr, colind, bias,
                                          out, n);
}

// round 3
// speedup vs baseline: 1.7784x; 1.3562x over previous
#include <cuda_runtime.h>
#include <cuda_bf16.h>
#include <cuda_fp16.h>

// GCNConv: out = D_in^{-1/2} * A * (D_out^{-1/2} * (X @ W)) + bias
// Stage 0: split W -> bf16 hi/lo, transposed [n][k], stride 136 (one small kernel)
// Stage 1: bf16x2-compensated HMMA GEMM  h = (X @ W) * out_norm  -> fp16 scratch
// Stage 2: gather-aggregate (fp16 reads)  out[i] = in_norm * sum h[colind[e]] + bias

#define MAX_N 100000
#define WT_STRIDE 136   // bf16 elements per transposed-W row (128 + 8 pad)
#define AS_STRIDE 132   // fp32 elements per A row in smem

__device__ __half         g_h[(size_t)MAX_N * 128];
__device__ __nv_bfloat16  g_whi[128 * WT_STRIDE];
__device__ __nv_bfloat16  g_wlo[128 * WT_STRIDE];

// ---------------------------------------------------------------------------
// helpers
// ---------------------------------------------------------------------------
// pack two floats into bf16x2 (v.x -> lower half = even k, v.y -> upper)
// and produce the residual (lo) pair the same way.
__device__ __forceinline__ void split_bf16x2(float2 v, unsigned& hi, unsigned& lo) {
    asm("cvt.rn.bf16x2.f32 %0, %1, %2;" : "=r"(hi) : "f"(v.y), "f"(v.x));
    float rx = v.x - __uint_as_float(hi << 16);
    float ry = v.y - __uint_as_float(hi & 0xffff0000u);
    asm("cvt.rn.bf16x2.f32 %0, %1, %2;" : "=r"(lo) : "f"(ry), "f"(rx));
}

__device__ __forceinline__ void mma_bf16(float* c, const unsigned* a,
                                         unsigned b0, unsigned b1) {
    asm volatile(
        "mma.sync.aligned.m16n8k16.row.col.f32.bf16.bf16.f32 "
        "{%0,%1,%2,%3}, {%4,%5,%6,%7}, {%8,%9}, {%0,%1,%2,%3};"
        : "+f"(c[0]), "+f"(c[1]), "+f"(c[2]), "+f"(c[3])
        : "r"(a[0]), "r"(a[1]), "r"(a[2]), "r"(a[3]), "r"(b0), "r"(b1));
}

// ---------------------------------------------------------------------------
// Stage 0: W [k][n] fp32 row-major -> Wt_hi/Wt_lo [n][k] bf16, stride 136
// ---------------------------------------------------------------------------
__global__ __launch_bounds__(256) void split_w_kernel(const float* __restrict__ w) {
    int idx = blockIdx.x * 256 + threadIdx.x;   // 0 .. 16383
    int k = idx >> 7;
    int nn = idx & 127;
    float f = w[idx];
    __nv_bfloat16 hi = __float2bfloat16(f);
    float lo = f - __bfloat162float(hi);
    g_whi[nn * WT_STRIDE + k] = hi;
    g_wlo[nn * WT_STRIDE + k] = __float2bfloat16(lo);
}

// ---------------------------------------------------------------------------
// Stage 1 GEMM: block = 128 rows x 128 cols, K=128, 512 threads (16 warps).
// warp_m = wid & 7 (16 rows), warp_n = wid >> 3 (64 cols -> 8 m16n8 tiles).
// bf16x2 compensation: hi*hi + lo*hi + hi*lo  (3 HMMAs per tile per k-step).
// ---------------------------------------------------------------------------
__global__ __launch_bounds__(512) void gemm_norm_kernel(
    const float* __restrict__ x,      // [n, 128]
    const int*   __restrict__ colptr, // [n+1]  (out-degree)
    __half*      __restrict__ h,      // [n, 128] fp16
    int n)
{
    extern __shared__ float smem[];
    float* As = smem;                                        // [128][132] fp32
    __nv_bfloat16* Whs = reinterpret_cast<__nv_bfloat16*>(smem + 128 * AS_STRIDE);
    __nv_bfloat16* Wls = Whs + 128 * WT_STRIDE;

    const int tid = threadIdx.x;
    const int block_row = blockIdx.x * 128;

    // --- stage A tile: 128 x 128 floats = 4096 float4 ---
    {
        const float4* x4 = reinterpret_cast<const float4*>(x);
        #pragma unroll
        for (int it = 0; it < 8; it++) {
            int elem = it * 512 + tid;
            int row  = elem >> 5;
            int col4 = elem & 31;
            int grow = block_row + row;
            float4 v = make_float4(0.f, 0.f, 0.f, 0.f);
            if (grow < n) v = x4[(size_t)grow * 32 + col4];
            *reinterpret_cast<float4*>(&As[row * AS_STRIDE + col4 * 4]) = v;
        }
    }
    // --- stage W hi/lo: each 128*136 bf16 = 2176 uint4 ---
    {
        const uint4* shi = reinterpret_cast<const uint4*>(g_whi);
        const uint4* slo = reinterpret_cast<const uint4*>(g_wlo);
        uint4* dhi = reinterpret_cast<uint4*>(Whs);
        uint4* dlo = reinterpret_cast<uint4*>(Wls);
        for (int i = tid; i < 2176; i += 512) {
            dhi[i] = shi[i];
            dlo[i] = slo[i];
        }
    }
    __syncthreads();

    const int warp_id = tid >> 5;
    const int lane    = tid & 31;
    const int warp_m  = warp_id & 7;          // rows warp_m*16
    const int warp_n  = warp_id >> 3;         // cols warp_n*64
    const int lg      = lane >> 2;            // 0..7
    const int lt      = lane & 3;             // 0..3

    float acc[8][4];
    #pragma unroll
    for (int t = 0; t < 8; t++)
        #pragma unroll
        for (int j = 0; j < 4; j++)
            acc[t][j] = 0.f;

    const int ar = warp_m * 16 + lg;          // a-frag base row in tile
    const int nbase = warp_n * 64;

    #pragma unroll
    for (int ks = 0; ks < 8; ks++) {
        const int k0 = ks * 16;

        // A fragments (m16 x k16): 4 float2, split each into bf16x2 hi/lo
        float2 v0 = *reinterpret_cast<const float2*>(&As[(ar    ) * AS_STRIDE + k0 + 2 * lt]);
        float2 v1 = *reinterpret_cast<const float2*>(&As[(ar + 8) * AS_STRIDE + k0 + 2 * lt]);
        float2 v2 = *reinterpret_cast<const float2*>(&As[(ar    ) * AS_STRIDE + k0 + 8 + 2 * lt]);
        float2 v3 = *reinterpret_cast<const float2*>(&As[(ar + 8) * AS_STRIDE + k0 + 8 + 2 * lt]);

        unsigned a_hi[4], a_lo[4];
        split_bf16x2(v0, a_hi[0], a_lo[0]);
        split_bf16x2(v1, a_hi[1], a_lo[1]);
        split_bf16x2(v2, a_hi[2], a_lo[2]);
        split_bf16x2(v3, a_hi[3], a_lo[3]);

        #pragma unroll
        for (int t = 0; t < 8; t++) {
            const int n0 = nbase + t * 8;
            const int boff = (n0 + lg) * WT_STRIDE + k0 + 2 * lt;
            unsigned bh0 = *reinterpret_cast<const unsigned*>(&Whs[boff]);
            unsigned bh1 = *reinterpret_cast<const unsigned*>(&Whs[boff + 8]);
            unsigned bl0 = *reinterpret_cast<const unsigned*>(&Wls[boff]);
            unsigned bl1 = *reinterpret_cast<const unsigned*>(&Wls[boff + 8]);

            mma_bf16(acc[t], a_hi, bh0, bh1);   // hi*hi
            mma_bf16(acc[t], a_lo, bh0, bh1);   // lo*hi
            mma_bf16(acc[t], a_hi, bl0, bl1);   // hi*lo
        }
    }

    // --- epilogue: scale rows by out_norm (1/sqrt(out-degree)), fp16 store ---
    const int row0 = block_row + warp_m * 16 + lg;
    const int row1 = row0 + 8;
    float s0 = 0.f, s1 = 0.f;
    if (row0 < n) {
        float d = (float)(colptr[row0 + 1] - colptr[row0]);
        s0 = (d > 0.f) ? rsqrtf(d) : 0.f;
    }
    if (row1 < n) {
        float d = (float)(colptr[row1 + 1] - colptr[row1]);
        s1 = (d > 0.f) ? rsqrtf(d) : 0.f;
    }

    #pragma unroll
    for (int t = 0; t < 8; t++) {
        const int col = nbase + t * 8 + 2 * lt;
        if (row0 < n) {
            __half2 p = __floats2half2_rn(acc[t][0] * s0, acc[t][1] * s0);
            *reinterpret_cast<__half2*>(&h[(size_t)row0 * 128 + col]) = p;
        }
        if (row1 < n) {
            __half2 p = __floats2half2_rn(acc[t][2] * s1, acc[t][3] * s1);
            *reinterpret_cast<__half2*>(&h[(size_t)row1 * 128 + col]) = p;
        }
    }
}

// ---------------------------------------------------------------------------
// Stage 2: aggregation. 8 nodes/block (256 thr), 32 lanes/node, uint2 (4 fp16)
// per lane per edge. Accumulate fp32.
// ---------------------------------------------------------------------------
__global__ __launch_bounds__(256) void aggregate_kernel(
    const __half* __restrict__ h,      // [n, 128] fp16
    const int*    __restrict__ rowptr, // [n+1]
    const int*    __restrict__ colind, // [E]
    const float*  __restrict__ bias,   // [128]
    float*        __restrict__ out,    // [n, 128]
    int n)
{
    const int node = blockIdx.x * 8 + (threadIdx.x >> 5);
    const int lane = threadIdx.x & 31;
    if (node >= n) return;

    const int beg = rowptr[node];
    const int end = rowptr[node + 1];

    const uint2* h2 = reinterpret_cast<const uint2*>(h);   // 4 halves per uint2

    float4 acc = make_float4(0.f, 0.f, 0.f, 0.f);

    int e = beg;
    for (; e + 4 <= end; e += 4) {
        int i0 = __ldg(&colind[e + 0]);
        int i1 = __ldg(&colind[e + 1]);
        int i2 = __ldg(&colind[e + 2]);
        int i3 = __ldg(&colind[e + 3]);
        uint2 u0 = h2[(size_t)i0 * 32 + lane];
        uint2 u1 = h2[(size_t)i1 * 32 + lane];
        uint2 u2 = h2[(size_t)i2 * 32 + lane];
        uint2 u3 = h2[(size_t)i3 * 32 + lane];

        float2 f;
        f = __half22float2(*reinterpret_cast<__half2*>(&u0.x)); acc.x += f.x; acc.y += f.y;
        f = __half22float2(*reinterpret_cast<__half2*>(&u0.y)); acc.z += f.x; acc.w += f.y;
        f = __half22float2(*reinterpret_cast<__half2*>(&u1.x)); acc.x += f.x; acc.y += f.y;
        f = __half22float2(*reinterpret_cast<__half2*>(&u1.y)); acc.z += f.x; acc.w += f.y;
        f = __half22float2(*reinterpret_cast<__half2*>(&u2.x)); acc.x += f.x; acc.y += f.y;
        f = __half22float2(*reinterpret_cast<__half2*>(&u2.y)); acc.z += f.x; acc.w += f.y;
        f = __half22float2(*reinterpret_cast<__half2*>(&u3.x)); acc.x += f.x; acc.y += f.y;
        f = __half22float2(*reinterpret_cast<__half2*>(&u3.y)); acc.z += f.x; acc.w += f.y;
    }
    for (; e < end; e++) {
        int i0 = __ldg(&colind[e]);
        uint2 u0 = h2[(size_t)i0 * 32 + lane];
        float2 f;
        f = __half22float2(*reinterpret_cast<__half2*>(&u0.x)); acc.x += f.x; acc.y += f.y;
        f = __half22float2(*reinterpret_cast<__half2*>(&u0.y)); acc.z += f.x; acc.w += f.y;
    }

    float deg = (float)(end - beg);
    float s = (deg > 0.f) ? rsqrtf(deg) : 0.f;

    float4 b = reinterpret_cast<const float4*>(bias)[lane];
    float4 o;
    o.x = acc.x * s + b.x;
    o.y = acc.y * s + b.y;
    o.z = acc.z * s + b.z;
    o.w = acc.w * s + b.w;

    reinterpret_cast<float4*>(out)[(size_t)node * 32 + lane] = o;
}

// ---------------------------------------------------------------------------
// launch
// ---------------------------------------------------------------------------
extern "C" void kernel_launch(void* const* d_in, const int* in_sizes, int n_in,
                              void* d_out, int out_size)
{
    const float* x      = (const float*)d_in[0];
    const float* weight = (const float*)d_in[1];
    const float* bias   = (const float*)d_in[2];
    const int*   rowptr = (const int*)  d_in[3];
    const int*   colind = (const int*)  d_in[4];
    const int*   colptr = (const int*)  d_in[5];

    const int n = in_sizes[3] - 1;

    float* out = (float*)d_out;

    __half* h_scratch = nullptr;
    cudaGetSymbolAddress((void**)&h_scratch, g_h);

    // Stage 0: split W (16384 elements)
    split_w_kernel<<<64, 256>>>(weight);

    // Stage 1: GEMM
    const int smem_bytes = 128 * AS_STRIDE * (int)sizeof(float)
                         + 2 * 128 * WT_STRIDE * (int)sizeof(__nv_bfloat16);
    cudaFuncSetAttribute(gemm_norm_kernel,
                         cudaFuncAttributeMaxDynamicSharedMemorySize, smem_bytes);
    int gemm_blocks = (n + 127) / 128;
    gemm_norm_kernel<<<gemm_blocks, 512, smem_bytes>>>(x, colptr, h_scratch, n);

    // Stage 2: aggregate
    int agg_blocks = (n + 7) / 8;
    aggregate_kernel<<<agg_blocks, 256>>>(h_scratch, rowptr, colind, bias,
                                          out, n);
}

// round 6
// speedup vs baseline: 1.9431x; 1.0926x over previous
#include <cuda_runtime.h>
#include <cuda_bf16.h>
#include <cuda_fp16.h>
#include <cstdint>
#include <cstring>

// GCNConv: out = D_in^{-1/2} * A * (D_out^{-1/2} * (X @ W)) + bias
// Stage 0: bake W into per-thread bf16 hi/lo MMA frag layout (64KB global)
// Stage 1: zero-smem bf16x3-compensated mma.sync GEMM, A from global w/ prefetch
//          h = (X @ W) * out_norm -> fp16 scratch
// Stage 2: gather-aggregate (fp16 reads)

#define MAX_N 100000

__device__ __half g_h[(size_t)MAX_N * 128];
// frag layout: [ntile 0..15][kstep 0..7][lane 0..31] = {bh0, bh1, bl0, bl1}
__device__ uint4  g_wfrag[16 * 8 * 32];

// ---------------------------------------------------------------------------
// helpers
// ---------------------------------------------------------------------------
// pack two floats -> bf16x2 (first arg = low half)
__device__ __forceinline__ unsigned pack_bf2(float lo_e, float hi_e) {
    unsigned r;
    asm("cvt.rn.bf16x2.f32 %0, %1, %2;" : "=r"(r) : "f"(hi_e), "f"(lo_e));
    return r;
}

// split float2 -> bf16x2 hi + bf16x2 lo (residual)
__device__ __forceinline__ void split_bf16x2(float2 v, unsigned& hi, unsigned& lo) {
    asm("cvt.rn.bf16x2.f32 %0, %1, %2;" : "=r"(hi) : "f"(v.y), "f"(v.x));
    float rx = v.x - __uint_as_float(hi << 16);
    float ry = v.y - __uint_as_float(hi & 0xffff0000u);
    asm("cvt.rn.bf16x2.f32 %0, %1, %2;" : "=r"(lo) : "f"(ry), "f"(rx));
}

__device__ __forceinline__ void mma_bf16(float* c, const unsigned* a,
                                         unsigned b0, unsigned b1) {
    asm volatile(
        "mma.sync.aligned.m16n8k16.row.col.f32.bf16.bf16.f32 "
        "{%0,%1,%2,%3}, {%4,%5,%6,%7}, {%8,%9}, {%0,%1,%2,%3};"
        : "+f"(c[0]), "+f"(c[1]), "+f"(c[2]), "+f"(c[3])
        : "r"(a[0]), "r"(a[1]), "r"(a[2]), "r"(a[3]), "r"(b0), "r"(b1));
}

__device__ __forceinline__ unsigned h2u(__half2 v) {
    unsigned r;
    memcpy(&r, &v, 4);
    return r;
}

// ---------------------------------------------------------------------------
// Stage 0: bake W [k][n] fp32 row-major into per-thread frag layout.
// For (ntile, kstep, lane): lg=lane>>2, lt=lane&3, n = ntile*8+lg, k0=kstep*16+2lt
//   bh0 = bf16x2(W[k0][n],   W[k0+1][n])      (low = even k)
//   bh1 = bf16x2(W[k0+8][n], W[k0+9][n])
//   bl0/bl1 = residuals
// ---------------------------------------------------------------------------
__global__ __launch_bounds__(256) void wfrag_kernel(const float* __restrict__ w) {
    int idx = blockIdx.x * 256 + threadIdx.x;   // 0..4095
    int lane  = idx & 31;
    int kstep = (idx >> 5) & 7;
    int ntile = idx >> 8;
    int lg = lane >> 2;
    int lt = lane & 3;
    int nn = ntile * 8 + lg;
    int k0 = kstep * 16 + 2 * lt;

    float f00 = w[(k0    ) * 128 + nn];
    float f01 = w[(k0 + 1) * 128 + nn];
    float f10 = w[(k0 + 8) * 128 + nn];
    float f11 = w[(k0 + 9) * 128 + nn];

    unsigned bh0, bl0, bh1, bl1;
    split_bf16x2(make_float2(f00, f01), bh0, bl0);
    split_bf16x2(make_float2(f10, f11), bh1, bl1);

    g_wfrag[idx] = make_uint4(bh0, bh1, bl0, bl1);
}

// ---------------------------------------------------------------------------
// Stage 1 GEMM: zero smem. Block = 64 rows x 128 cols, 256 threads = 8 warps:
// warp_m = wid>>2 (2 groups of 32 rows), warp_n = wid&3 (4 groups of 32 cols).
// Warp tile = 32 rows (2 m16) x 32 cols (4 n8). 3-term bf16 compensation.
// A-frags from global (prefetch next kstep), B-frags from L1-resident g_wfrag.
// ---------------------------------------------------------------------------
__global__ __launch_bounds__(256, 2) void gemm_mma_kernel(
    const float* __restrict__ x,       // [n,128]
    const uint4* __restrict__ wfrag,   // baked W frags
    const int*   __restrict__ colptr,  // [n+1]
    __half*      __restrict__ h,       // [n,128]
    int n)
{
    const int tid  = threadIdx.x;
    const int wid  = tid >> 5;
    const int lane = tid & 31;
    const int lg   = lane >> 2;
    const int lt   = lane & 3;
    const int warp_m = wid >> 2;            // 0..1
    const int warp_n = wid & 3;             // 0..3
    const int rowbase = blockIdx.x * 64 + warp_m * 32;
    const int colbase = warp_n * 32;

    // row indices for the two m-tiles (each m-tile uses rows r, r+8)
    int rA0 = rowbase + lg;        // m-tile 0
    int rB0 = rA0 + 8;
    int rA1 = rA0 + 16;            // m-tile 1
    int rB1 = rB0 + 16;
    const bool vA0 = rA0 < n, vB0 = rB0 < n, vA1 = rA1 < n, vB1 = rB1 < n;

    const float2* xA0 = reinterpret_cast<const float2*>(x + (size_t)rA0 * 128);
    const float2* xB0 = reinterpret_cast<const float2*>(x + (size_t)rB0 * 128);
    const float2* xA1 = reinterpret_cast<const float2*>(x + (size_t)rA1 * 128);
    const float2* xB1 = reinterpret_cast<const float2*>(x + (size_t)rB1 * 128);

    float acc[2][4][4];
    #pragma unroll
    for (int mt = 0; mt < 2; mt++)
        #pragma unroll
        for (int nt = 0; nt < 4; nt++)
            #pragma unroll
            for (int j = 0; j < 4; j++)
                acc[mt][nt][j] = 0.f;

    const float2 z2 = make_float2(0.f, 0.f);

    // prefetch buffer: pa[mt][j] : j0=(rowA,klo) j1=(rowB,klo) j2=(rowA,khi) j3=(rowB,khi)
    float2 pa[2][4];
    {
        const int kq = lt;                       // float2 index of k0+2lt
        pa[0][0] = vA0 ? xA0[kq]     : z2;
        pa[0][1] = vB0 ? xB0[kq]     : z2;
        pa[0][2] = vA0 ? xA0[kq + 4] : z2;
        pa[0][3] = vB0 ? xB0[kq + 4] : z2;
        pa[1][0] = vA1 ? xA1[kq]     : z2;
        pa[1][1] = vB1 ? xB1[kq]     : z2;
        pa[1][2] = vA1 ? xA1[kq + 4] : z2;
        pa[1][3] = vB1 ? xB1[kq + 4] : z2;
    }

    const uint4* wf_base = wfrag + ((size_t)warp_n * 4 * 8 + 0) * 32 + lane;

    #pragma unroll
    for (int s = 0; s < 8; s++) {
        // split current A frags
        unsigned a_hi[2][4], a_lo[2][4];
        #pragma unroll
        for (int mt = 0; mt < 2; mt++)
            #pragma unroll
            for (int j = 0; j < 4; j++)
                split_bf16x2(pa[mt][j], a_hi[mt][j], a_lo[mt][j]);

        // prefetch next kstep
        if (s < 7) {
            const int kq = (s + 1) * 8 + lt;
            pa[0][0] = vA0 ? xA0[kq]     : z2;
            pa[0][1] = vB0 ? xB0[kq]     : z2;
            pa[0][2] = vA0 ? xA0[kq + 4] : z2;
            pa[0][3] = vB0 ? xB0[kq + 4] : z2;
            pa[1][0] = vA1 ? xA1[kq]     : z2;
            pa[1][1] = vB1 ? xB1[kq]     : z2;
            pa[1][2] = vA1 ? xA1[kq + 4] : z2;
            pa[1][3] = vB1 ? xB1[kq + 4] : z2;
        }

        #pragma unroll
        for (int nt = 0; nt < 4; nt++) {
            uint4 b = wf_base[(nt * 8 + s) * 32];
            #pragma unroll
            for (int mt = 0; mt < 2; mt++) {
                mma_bf16(acc[mt][nt], a_hi[mt], b.x, b.y);   // hi*hi
                mma_bf16(acc[mt][nt], a_lo[mt], b.x, b.y);   // lo*hi
                mma_bf16(acc[mt][nt], a_hi[mt], b.z, b.w);   // hi*lo
            }
        }
    }

    // --- epilogue: scale by out_norm, fp16 half2 stores ---
    #pragma unroll
    for (int mt = 0; mt < 2; mt++) {
        const int row0 = rowbase + mt * 16 + lg;
        const int row1 = row0 + 8;
        float s0 = 0.f, s1 = 0.f;
        if (row0 < n) {
            float d = (float)(colptr[row0 + 1] - colptr[row0]);
            s0 = (d > 0.f) ? rsqrtf(d) : 0.f;
        }
        if (row1 < n) {
            float d = (float)(colptr[row1 + 1] - colptr[row1]);
            s1 = (d > 0.f) ? rsqrtf(d) : 0.f;
        }
        #pragma unroll
        for (int nt = 0; nt < 4; nt++) {
            const int col = colbase + nt * 8 + 2 * lt;
            if (row0 < n) {
                __half2 p = __floats2half2_rn(acc[mt][nt][0] * s0,
                                              acc[mt][nt][1] * s0);
                *reinterpret_cast<unsigned*>(&h[(size_t)row0 * 128 + col]) = h2u(p);
            }
            if (row1 < n) {
                __half2 p = __floats2half2_rn(acc[mt][nt][2] * s1,
                                              acc[mt][nt][3] * s1);
                *reinterpret_cast<unsigned*>(&h[(size_t)row1 * 128 + col]) = h2u(p);
            }
        }
    }
}

// ---------------------------------------------------------------------------
// Stage 2: aggregation. 8 nodes/block (256 thr), 32 lanes/node, uint2 fp16
// loads, fp32 accumulate.
// ---------------------------------------------------------------------------
__global__ __launch_bounds__(256) void aggregate_kernel(
    const __half* __restrict__ h,
    const int*    __restrict__ rowptr,
    const int*    __restrict__ colind,
    const float*  __restrict__ bias,
    float*        __restrict__ out,
    int n)
{
    const int node = blockIdx.x * 8 + (threadIdx.x >> 5);
    const int lane = threadIdx.x & 31;
    if (node >= n) return;

    const int beg = rowptr[node];
    const int end = rowptr[node + 1];
    const uint2* h2 = reinterpret_cast<const uint2*>(h);

    float4 acc = make_float4(0.f, 0.f, 0.f, 0.f);

    int e = beg;
    for (; e + 4 <= end; e += 4) {
        int i0 = __ldg(&colind[e + 0]);
        int i1 = __ldg(&colind[e + 1]);
        int i2 = __ldg(&colind[e + 2]);
        int i3 = __ldg(&colind[e + 3]);
        uint2 u0 = h2[(size_t)i0 * 32 + lane];
        uint2 u1 = h2[(size_t)i1 * 32 + lane];
        uint2 u2 = h2[(size_t)i2 * 32 + lane];
        uint2 u3 = h2[(size_t)i3 * 32 + lane];
        float2 f;
        f = __half22float2(*reinterpret_cast<__half2*>(&u0.x)); acc.x += f.x; acc.y += f.y;
        f = __half22float2(*reinterpret_cast<__half2*>(&u0.y)); acc.z += f.x; acc.w += f.y;
        f = __half22float2(*reinterpret_cast<__half2*>(&u1.x)); acc.x += f.x; acc.y += f.y;
        f = __half22float2(*reinterpret_cast<__half2*>(&u1.y)); acc.z += f.x; acc.w += f.y;
        f = __half22float2(*reinterpret_cast<__half2*>(&u2.x)); acc.x += f.x; acc.y += f.y;
        f = __half22float2(*reinterpret_cast<__half2*>(&u2.y)); acc.z += f.x; acc.w += f.y;
        f = __half22float2(*reinterpret_cast<__half2*>(&u3.x)); acc.x += f.x; acc.y += f.y;
        f = __half22float2(*reinterpret_cast<__half2*>(&u3.y)); acc.z += f.x; acc.w += f.y;
    }
    for (; e < end; e++) {
        int i0 = __ldg(&colind[e]);
        uint2 u0 = h2[(size_t)i0 * 32 + lane];
        float2 f;
        f = __half22float2(*reinterpret_cast<__half2*>(&u0.x)); acc.x += f.x; acc.y += f.y;
        f = __half22float2(*reinterpret_cast<__half2*>(&u0.y)); acc.z += f.x; acc.w += f.y;
    }

    float deg = (float)(end - beg);
    float s = (deg > 0.f) ? rsqrtf(deg) : 0.f;

    float4 b = reinterpret_cast<const float4*>(bias)[lane];
    float4 o;
    o.x = acc.x * s + b.x;
    o.y = acc.y * s + b.y;
    o.z = acc.z * s + b.z;
    o.w = acc.w * s + b.w;

    reinterpret_cast<float4*>(out)[(size_t)node * 32 + lane] = o;
}

// ---------------------------------------------------------------------------
// launch
// ---------------------------------------------------------------------------
extern "C" void kernel_launch(void* const* d_in, const int* in_sizes, int n_in,
                              void* d_out, int out_size)
{
    const float* x      = (const float*)d_in[0];
    const float* weight = (const float*)d_in[1];
    const float* bias   = (const float*)d_in[2];
    const int*   rowptr = (const int*)  d_in[3];
    const int*   colind = (const int*)  d_in[4];
    const int*   colptr = (const int*)  d_in[5];

    const int n = in_sizes[3] - 1;
    float* out = (float*)d_out;

    __half* h_scratch = nullptr;
    cudaGetSymbolAddress((void**)&h_scratch, g_h);
    uint4* wfrag = nullptr;
    cudaGetSymbolAddress((void**)&wfrag, g_wfrag);

    // Stage 0: bake W frags (4096 uint4)
    wfrag_kernel<<<16, 256>>>(weight);

    // Stage 1: GEMM
    int gemm_blocks = (n + 63) / 64;
    gemm_mma_kernel<<<gemm_blocks, 256>>>(x, wfrag, colptr, h_scratch, n);

    // Stage 2: aggregate
    int agg_blocks = (n + 7) / 8;
    aggregate_kernel<<<agg_blocks, 256>>>(h_scratch, rowptr, colind, bias,
                                          out, n);
}

// round 7
// speedup vs baseline: 2.0707x; 1.0657x over previous
#include <cuda_runtime.h>
#include <cuda_bf16.h>
#include <cuda_fp16.h>
#include <cstdint>
#include <cstring>

// GCNConv: out = D_in^{-1/2} * A * (D_out^{-1/2} * (X @ W)) + bias
// Stage 0: bake W into per-thread bf16 hi/lo MMA frag layout (64KB global)
// Stage 1: zero-smem bf16x3 mma.sync GEMM; each warp owns 16 rows x 128 cols
//          (X read exactly once), B-frags L1-resident.
// Stage 2: gather-aggregate (fp16 reads)

#define MAX_N 100000

__device__ __half g_h[(size_t)MAX_N * 128];
// frag layout: [ntile 0..15][kstep 0..7][lane 0..31] = {bh0, bh1, bl0, bl1}
__device__ uint4  g_wfrag[16 * 8 * 32];

// ---------------------------------------------------------------------------
// helpers
// ---------------------------------------------------------------------------
// split float2 -> bf16x2 hi + bf16x2 lo (residual); .x = low half
__device__ __forceinline__ void split_bf16x2(float2 v, unsigned& hi, unsigned& lo) {
    asm("cvt.rn.bf16x2.f32 %0, %1, %2;" : "=r"(hi) : "f"(v.y), "f"(v.x));
    float rx = v.x - __uint_as_float(hi << 16);
    float ry = v.y - __uint_as_float(hi & 0xffff0000u);
    asm("cvt.rn.bf16x2.f32 %0, %1, %2;" : "=r"(lo) : "f"(ry), "f"(rx));
}

__device__ __forceinline__ void mma_bf16(float* c, const unsigned* a,
                                         unsigned b0, unsigned b1) {
    asm volatile(
        "mma.sync.aligned.m16n8k16.row.col.f32.bf16.bf16.f32 "
        "{%0,%1,%2,%3}, {%4,%5,%6,%7}, {%8,%9}, {%0,%1,%2,%3};"
        : "+f"(c[0]), "+f"(c[1]), "+f"(c[2]), "+f"(c[3])
        : "r"(a[0]), "r"(a[1]), "r"(a[2]), "r"(a[3]), "r"(b0), "r"(b1));
}

__device__ __forceinline__ unsigned h2u(__half2 v) {
    unsigned r;
    memcpy(&r, &v, 4);
    return r;
}

// ---------------------------------------------------------------------------
// Stage 0: bake W [k][n] fp32 row-major into per-thread frag layout.
// (ntile, kstep, lane): lg=lane>>2, lt=lane&3, n = ntile*8+lg, k0=kstep*16+2lt
//   bh0 = bf16x2(W[k0][n], W[k0+1][n]);  bh1 = bf16x2(W[k0+8][n], W[k0+9][n])
//   bl0/bl1 = residuals
// ---------------------------------------------------------------------------
__global__ __launch_bounds__(256) void wfrag_kernel(const float* __restrict__ w) {
    int idx = blockIdx.x * 256 + threadIdx.x;   // 0..4095
    int lane  = idx & 31;
    int kstep = (idx >> 5) & 7;
    int ntile = idx >> 8;
    int lg = lane >> 2;
    int lt = lane & 3;
    int nn = ntile * 8 + lg;
    int k0 = kstep * 16 + 2 * lt;

    float f00 = w[(k0    ) * 128 + nn];
    float f01 = w[(k0 + 1) * 128 + nn];
    float f10 = w[(k0 + 8) * 128 + nn];
    float f11 = w[(k0 + 9) * 128 + nn];

    unsigned bh0, bl0, bh1, bl1;
    split_bf16x2(make_float2(f00, f01), bh0, bl0);
    split_bf16x2(make_float2(f10, f11), bh1, bl1);

    g_wfrag[idx] = make_uint4(bh0, bh1, bl0, bl1);
}

// ---------------------------------------------------------------------------
// Stage 1 GEMM: zero smem. Block = 128 rows, 8 warps; warp owns rows
// [wid*16, wid*16+16) x cols [0,128) = 16 n8-tiles. 3-term bf16 compensation.
// A-frags straight from global (each row read once per grid), B-frags from
// L1-resident g_wfrag (shared across all warps on the SM).
// ---------------------------------------------------------------------------
__global__ __launch_bounds__(256, 2) void gemm_mma_kernel(
    const float* __restrict__ x,       // [n,128]
    const uint4* __restrict__ wfrag,   // baked W frags
    const int*   __restrict__ colptr,  // [n+1]
    __half*      __restrict__ h,       // [n,128]
    int n)
{
    const int tid  = threadIdx.x;
    const int wid  = tid >> 5;
    const int lane = tid & 31;
    const int lg   = lane >> 2;
    const int lt   = lane & 3;
    const int rowbase = blockIdx.x * 128 + wid * 16;

    const int r0 = rowbase + lg;       // rows r0, r0+8
    const int r1 = r0 + 8;
    const bool v0 = r0 < n, v1 = r1 < n;

    const float2* xr0 = reinterpret_cast<const float2*>(x + (size_t)r0 * 128);
    const float2* xr1 = reinterpret_cast<const float2*>(x + (size_t)r1 * 128);

    float acc[16][4];
    #pragma unroll
    for (int nt = 0; nt < 16; nt++)
        #pragma unroll
        for (int j = 0; j < 4; j++)
            acc[nt][j] = 0.f;

    const float2 z2 = make_float2(0.f, 0.f);

    // A prefetch: j0=(r0,klo) j1=(r1,klo) j2=(r0,khi) j3=(r1,khi)
    float2 pa[4];
    pa[0] = v0 ? xr0[lt]     : z2;
    pa[1] = v1 ? xr1[lt]     : z2;
    pa[2] = v0 ? xr0[lt + 4] : z2;
    pa[3] = v1 ? xr1[lt + 4] : z2;

    const uint4* wf = wfrag + lane;

    #pragma unroll
    for (int s = 0; s < 8; s++) {
        unsigned a_hi[4], a_lo[4];
        #pragma unroll
        for (int j = 0; j < 4; j++)
            split_bf16x2(pa[j], a_hi[j], a_lo[j]);

        if (s < 7) {
            const int kq = (s + 1) * 8 + lt;
            pa[0] = v0 ? xr0[kq]     : z2;
            pa[1] = v1 ? xr1[kq]     : z2;
            pa[2] = v0 ? xr0[kq + 4] : z2;
            pa[3] = v1 ? xr1[kq + 4] : z2;
        }

        #pragma unroll
        for (int nt = 0; nt < 16; nt++) {
            uint4 b = wf[(nt * 8 + s) * 32];
            mma_bf16(acc[nt], a_hi, b.x, b.y);   // hi*hi
            mma_bf16(acc[nt], a_lo, b.x, b.y);   // lo*hi
            mma_bf16(acc[nt], a_hi, b.z, b.w);   // hi*lo
        }
    }

    // --- epilogue: scale by out_norm (1/sqrt(out-degree)), fp16 stores ---
    float s0 = 0.f, s1 = 0.f;
    if (v0) {
        float d = (float)(colptr[r0 + 1] - colptr[r0]);
        s0 = (d > 0.f) ? rsqrtf(d) : 0.f;
    }
    if (v1) {
        float d = (float)(colptr[r1 + 1] - colptr[r1]);
        s1 = (d > 0.f) ? rsqrtf(d) : 0.f;
    }

    #pragma unroll
    for (int nt = 0; nt < 16; nt++) {
        const int col = nt * 8 + 2 * lt;
        if (v0) {
            __half2 p = __floats2half2_rn(acc[nt][0] * s0, acc[nt][1] * s0);
            *reinterpret_cast<unsigned*>(&h[(size_t)r0 * 128 + col]) = h2u(p);
        }
        if (v1) {
            __half2 p = __floats2half2_rn(acc[nt][2] * s1, acc[nt][3] * s1);
            *reinterpret_cast<unsigned*>(&h[(size_t)r1 * 128 + col]) = h2u(p);
        }
    }
}

// ---------------------------------------------------------------------------
// Stage 2: aggregation. 8 nodes/block (256 thr), 32 lanes/node, uint2 fp16
// loads, fp32 accumulate.
// ---------------------------------------------------------------------------
__global__ __launch_bounds__(256) void aggregate_kernel(
    const __half* __restrict__ h,
    const int*    __restrict__ rowptr,
    const int*    __restrict__ colind,
    const float*  __restrict__ bias,
    float*        __restrict__ out,
    int n)
{
    const int node = blockIdx.x * 8 + (threadIdx.x >> 5);
    const int lane = threadIdx.x & 31;
    if (node >= n) return;

    const int beg = rowptr[node];
    const int end = rowptr[node + 1];
    const uint2* h2 = reinterpret_cast<const uint2*>(h);

    float4 acc = make_float4(0.f, 0.f, 0.f, 0.f);

    int e = beg;
    for (; e + 4 <= end; e += 4) {
        int i0 = __ldg(&colind[e + 0]);
        int i1 = __ldg(&colind[e + 1]);
        int i2 = __ldg(&colind[e + 2]);
        int i3 = __ldg(&colind[e + 3]);
        uint2 u0 = h2[(size_t)i0 * 32 + lane];
        uint2 u1 = h2[(size_t)i1 * 32 + lane];
        uint2 u2 = h2[(size_t)i2 * 32 + lane];
        uint2 u3 = h2[(size_t)i3 * 32 + lane];
        float2 f;
        f = __half22float2(*reinterpret_cast<__half2*>(&u0.x)); acc.x += f.x; acc.y += f.y;
        f = __half22float2(*reinterpret_cast<__half2*>(&u0.y)); acc.z += f.x; acc.w += f.y;
        f = __half22float2(*reinterpret_cast<__half2*>(&u1.x)); acc.x += f.x; acc.y += f.y;
        f = __half22float2(*reinterpret_cast<__half2*>(&u1.y)); acc.z += f.x; acc.w += f.y;
        f = __half22float2(*reinterpret_cast<__half2*>(&u2.x)); acc.x += f.x; acc.y += f.y;
        f = __half22float2(*reinterpret_cast<__half2*>(&u2.y)); acc.z += f.x; acc.w += f.y;
        f = __half22float2(*reinterpret_cast<__half2*>(&u3.x)); acc.x += f.x; acc.y += f.y;
        f = __half22float2(*reinterpret_cast<__half2*>(&u3.y)); acc.z += f.x; acc.w += f.y;
    }
    for (; e < end; e++) {
        int i0 = __ldg(&colind[e]);
        uint2 u0 = h2[(size_t)i0 * 32 + lane];
        float2 f;
        f = __half22float2(*reinterpret_cast<__half2*>(&u0.x)); acc.x += f.x; acc.y += f.y;
        f = __half22float2(*reinterpret_cast<__half2*>(&u0.y)); acc.z += f.x; acc.w += f.y;
    }

    float deg = (float)(end - beg);
    float s = (deg > 0.f) ? rsqrtf(deg) : 0.f;

    float4 b = reinterpret_cast<const float4*>(bias)[lane];
    float4 o;
    o.x = acc.x * s + b.x;
    o.y = acc.y * s + b.y;
    o.z = acc.z * s + b.z;
    o.w = acc.w * s + b.w;

    reinterpret_cast<float4*>(out)[(size_t)node * 32 + lane] = o;
}

// ---------------------------------------------------------------------------
// launch
// ---------------------------------------------------------------------------
extern "C" void kernel_launch(void* const* d_in, const int* in_sizes, int n_in,
                              void* d_out, int out_size)
{
    const float* x      = (const float*)d_in[0];
    const float* weight = (const float*)d_in[1];
    const float* bias   = (const float*)d_in[2];
    const int*   rowptr = (const int*)  d_in[3];
    const int*   colind = (const int*)  d_in[4];
    const int*   colptr = (const int*)  d_in[5];

    const int n = in_sizes[3] - 1;
    float* out = (float*)d_out;

    __half* h_scratch = nullptr;
    cudaGetSymbolAddress((void**)&h_scratch, g_h);
    uint4* wfrag = nullptr;
    cudaGetSymbolAddress((void**)&wfrag, g_wfrag);

    // Stage 0: bake W frags (4096 uint4)
    wfrag_kernel<<<16, 256>>>(weight);

    // Stage 1: GEMM (128 rows per block)
    int gemm_blocks = (n + 127) / 128;
    gemm_mma_kernel<<<gemm_blocks, 256>>>(x, wfrag, colptr, h_scratch, n);

    // Stage 2: aggregate
    int agg_blocks = (n + 7) / 8;
    aggregate_kernel<<<agg_blocks, 256>>>(h_scratch, rowptr, colind, bias,
                                          out, n);
}